// round 7
// baseline (speedup 1.0000x reference)
#include <cuda_runtime.h>

#define BB 64
#define TT 200
#define NS 1000
#define NCH 8
#define CS 25

// ---------------- device scratch ----------------
__device__ float2 g_Wsk[1000 * 32];   // (w[l], w[l+32]) per skill, softmaxed
__device__ float2 g_EA [2000 * 64];   // (e, a) per x-index, per d
__device__ float2 g_G  [1000 * 32];   // (g[l], g[l+32]) = k·fW2^T + fb
__device__ int    g_idx[BB * TT];     // skill | (x << 16)
__device__ float  g_read[BB * TT * 64];
__device__ float  g_A[BB * NCH * 64 * 64];   // chunk affine: scale,  [b][ch][d][m]
__device__ float  g_Bc[BB * NCH * 64 * 64];  // chunk affine: offset, [b][ch][d][m]

static __device__ __forceinline__ float tanh_a(float x) {
    float y; asm("tanh.approx.f32 %0, %1;" : "=f"(y) : "f"(x)); return y;
}
static __device__ __forceinline__ float sigmoid_e(float x) {
    return 1.0f / (1.0f + __expf(-x));
}

// =====================================================================
// Kernel P: precompute tables. 1 row per warp. (round-6 version)
// =====================================================================
__global__ __launch_bounds__(256) void k_pre(
    const int* __restrict__ skills, const int* __restrict__ responses,
    const float* __restrict__ k_emb, const float* __restrict__ v_emb,
    const float* __restrict__ Mk, const float* __restrict__ fW,
    const float* __restrict__ fb, const float* __restrict__ eW,
    const float* __restrict__ eb, const float* __restrict__ aW,
    const float* __restrict__ ab)
{
    __shared__ __align__(16) float W0[64 * 68];
    __shared__ __align__(16) float W1[64 * 68];

    int tid = threadIdx.x;
    int w = tid >> 5, l = tid & 31;
    bool isA = blockIdx.x < 125;
    int row = isA ? (blockIdx.x * 8 + w) : ((blockIdx.x - 125) * 8 + w);

    const float4* xp = isA ? (const float4*)&k_emb[row * 64]
                           : (const float4*)&v_emb[row * 64];
    float4 xr[16];
#pragma unroll
    for (int q = 0; q < 16; q++) xr[q] = xp[q];

    int gt = blockIdx.x * 256 + tid;
    if (gt < BB * TT) {
        int s = skills[gt], r = responses[gt];
        int mr = (r > -1) ? r : 0;
        g_idx[gt] = s | ((s + NS * mr) << 16);
    }

    {
        const float4* s0 = isA ? (const float4*)Mk : (const float4*)eW;
        const float4* s1f = (const float4*)fW;
        const float4* s1a = (const float4*)aW;
        float4 v0[4], v1[4];
#pragma unroll
        for (int k = 0; k < 4; k++) {
            int i = tid + k * 256;
            int o = i >> 4, q4 = i & 15;
            v0[k] = s0[i];
            v1[k] = isA ? s1f[o * 32 + 16 + q4] : s1a[i];
        }
#pragma unroll
        for (int k = 0; k < 4; k++) {
            int i = tid + k * 256;
            int o = i >> 4, q4 = i & 15;
            *(float4*)&W0[o * 68 + q4 * 4] = v0[k];
            *(float4*)&W1[o * 68 + q4 * 4] = v1[k];
        }
    }
    __syncthreads();

    const float4* pL0 = (const float4*)&W0[l * 68];
    const float4* pH0 = (const float4*)&W0[(l + 32) * 68];
    const float4* pL1 = (const float4*)&W1[l * 68];
    const float4* pH1 = (const float4*)&W1[(l + 32) * 68];

    float c0A = 0.f, c1A = 0.f, c2A = 0.f, c3A = 0.f;
    float c0B = 0.f, c1B = 0.f, c2B = 0.f, c3B = 0.f;
#pragma unroll
    for (int q = 0; q < 16; q += 2) {
        float4 xa = xr[q];
        float4 xb = xr[q + 1];
        float4 aL = pL0[q];  float4 aL2 = pL0[q + 1];
        float4 aH = pH0[q];  float4 aH2 = pH0[q + 1];
        float4 bL = pL1[q];  float4 bL2 = pL1[q + 1];
        float4 bH = pH1[q];  float4 bH2 = pH1[q + 1];
        c0A = fmaf(xa.x, aL.x, c0A); c0A = fmaf(xa.y, aL.y, c0A);
        c0A = fmaf(xa.z, aL.z, c0A); c0A = fmaf(xa.w, aL.w, c0A);
        c1A = fmaf(xa.x, aH.x, c1A); c1A = fmaf(xa.y, aH.y, c1A);
        c1A = fmaf(xa.z, aH.z, c1A); c1A = fmaf(xa.w, aH.w, c1A);
        c2A = fmaf(xa.x, bL.x, c2A); c2A = fmaf(xa.y, bL.y, c2A);
        c2A = fmaf(xa.z, bL.z, c2A); c2A = fmaf(xa.w, bL.w, c2A);
        c3A = fmaf(xa.x, bH.x, c3A); c3A = fmaf(xa.y, bH.y, c3A);
        c3A = fmaf(xa.z, bH.z, c3A); c3A = fmaf(xa.w, bH.w, c3A);
        c0B = fmaf(xb.x, aL2.x, c0B); c0B = fmaf(xb.y, aL2.y, c0B);
        c0B = fmaf(xb.z, aL2.z, c0B); c0B = fmaf(xb.w, aL2.w, c0B);
        c1B = fmaf(xb.x, aH2.x, c1B); c1B = fmaf(xb.y, aH2.y, c1B);
        c1B = fmaf(xb.z, aH2.z, c1B); c1B = fmaf(xb.w, aH2.w, c1B);
        c2B = fmaf(xb.x, bL2.x, c2B); c2B = fmaf(xb.y, bL2.y, c2B);
        c2B = fmaf(xb.z, bL2.z, c2B); c2B = fmaf(xb.w, bL2.w, c2B);
        c3B = fmaf(xb.x, bH2.x, c3B); c3B = fmaf(xb.y, bH2.y, c3B);
        c3B = fmaf(xb.z, bH2.z, c3B); c3B = fmaf(xb.w, bH2.w, c3B);
    }
    float c0 = c0A + c0B, c1 = c1A + c1B;
    float c2 = c2A + c2B, c3 = c3A + c3B;

    if (isA) {
        float e0 = __expf(c0), e1 = __expf(c1);
        float s = e0 + e1;
#pragma unroll
        for (int o = 16; o; o >>= 1) s += __shfl_xor_sync(~0u, s, o);
        float inv = 1.0f / s;
        g_Wsk[row * 32 + l] = make_float2(e0 * inv, e1 * inv);
        g_G[row * 32 + l]   = make_float2(c2 + fb[l], c3 + fb[l + 32]);
    } else {
        g_EA[row * 64 + l]      = make_float2(sigmoid_e(c0 + eb[l]),      tanhf(c2 + ab[l]));
        g_EA[row * 64 + l + 32] = make_float2(sigmoid_e(c1 + eb[l + 32]), tanhf(c3 + ab[l + 32]));
    }
}

// =====================================================================
// Kernel A: per-chunk affine composition (A,B) per (b,ch,m,d).
// block = (b, ch, dbase); warp = d; lane = m (and m+32). 4096 blocks.
// Mv_t = A*Mv_start + B over the chunk's 25 steps.
// =====================================================================
__global__ __launch_bounds__(256) void kA()
{
    __shared__ __align__(16) float2 w_s[CS][32];
    __shared__ __align__(16) float2 ea_s[CS][8];
    __shared__ int idx_s[CS];

    int tid = threadIdx.x;
    int w = tid >> 5, l = tid & 31;
    int b = blockIdx.x >> 6;
    int ch = (blockIdx.x >> 3) & 7;
    int dbase = (blockIdx.x & 7) << 3;
    int d = dbase + w;

    const int* idxp = g_idx + b * TT + ch * CS;
    if (tid < CS) idx_s[tid] = idxp[tid];
    __syncthreads();

#pragma unroll
    for (int k = 0; k < 4; k++) {
        int i = tid + k * 256;
        if (i < CS * 32) {
            int st = i >> 5, ll = i & 31;
            int p = idx_s[st];
            w_s[st][ll] = g_Wsk[(p & 0xffff) * 32 + ll];
        }
    }
    if (tid < CS * 8) {
        int st = tid >> 3, dd = tid & 7;
        int p = idx_s[st];
        ea_s[st][dd] = g_EA[(p >> 16) * 64 + dbase + dd];
    }
    __syncthreads();

    float A0 = 1.f, A1 = 1.f, B0 = 0.f, B1 = 0.f;
#pragma unroll
    for (int j = 0; j < CS; j++) {
        float2 w2 = w_s[j][l];
        float2 ea = ea_s[j][w];
        float al0 = fmaf(-w2.x, ea.x, 1.0f);
        float al1 = fmaf(-w2.y, ea.x, 1.0f);
        float wa0 = w2.x * ea.y;
        float wa1 = w2.y * ea.y;
        A0 *= al0;  A1 *= al1;
        B0 = fmaf(B0, al0, wa0);
        B1 = fmaf(B1, al1, wa1);
    }

    int base = ((b * NCH + ch) * 64 + d) * 64;
    g_A [base + l]      = A0;
    g_A [base + l + 32] = A1;
    g_Bc[base + l]      = B0;
    g_Bc[base + l + 32] = B1;
}

// =====================================================================
// Kernel C: chunk replay with reads. block = (b, ch, dbase); warp = d.
// Start state = Mv0 folded through prior chunks' (A,B). 25 steps,
// deferred transposed read-reduction (16 + 9 lanes).
// =====================================================================
__global__ __launch_bounds__(256) void kC(const float* __restrict__ Mv0)
{
    __shared__ __align__(16) float2 w_s[CS][32];     // 6.4KB
    __shared__ __align__(16) float2 ea_s[CS][8];     // 1.6KB
    __shared__ __align__(16) float  mv_s[64 * 9];    // 2.3KB
    __shared__ __align__(16) float  buf[8][CS][36];  // 28.8KB
    __shared__ int idx_s[CS];

    int tid = threadIdx.x;
    int w = tid >> 5, l = tid & 31;
    int b = blockIdx.x >> 6;
    int ch = (blockIdx.x >> 3) & 7;
    int dbase = (blockIdx.x & 7) << 3;
    int d = dbase + w;

    const int* idxp = g_idx + b * TT + ch * CS;
    if (tid < CS) idx_s[tid] = idxp[tid];
    // stage Mv0 columns [dbase, dbase+8) transposed: mv_s[m*9 + dd]
#pragma unroll
    for (int k = 0; k < 2; k++) {
        int i = tid + k * 256;
        int m = i >> 3, dd = i & 7;
        mv_s[m * 9 + dd] = Mv0[m * 64 + dbase + dd];
    }
    __syncthreads();

#pragma unroll
    for (int k = 0; k < 4; k++) {
        int i = tid + k * 256;
        if (i < CS * 32) {
            int st = i >> 5, ll = i & 31;
            int p = idx_s[st];
            w_s[st][ll] = g_Wsk[(p & 0xffff) * 32 + ll];
        }
    }
    if (tid < CS * 8) {
        int st = tid >> 3, dd = tid & 7;
        int p = idx_s[st];
        ea_s[st][dd] = g_EA[(p >> 16) * 64 + dbase + dd];
    }

    // start state: fold prior chunks
    float s0 = mv_s[l * 9 + w];
    float s1 = mv_s[(l + 32) * 9 + w];
    for (int c = 0; c < ch; c++) {
        int base = ((b * NCH + c) * 64 + d) * 64;
        float a0 = g_A[base + l],      b0 = g_Bc[base + l];
        float a1 = g_A[base + l + 32], b1 = g_Bc[base + l + 32];
        s0 = fmaf(a0, s0, b0);
        s1 = fmaf(a1, s1, b1);
    }
    __syncthreads();

    float (*mybuf)[36] = buf[w];
#pragma unroll
    for (int j = 0; j < CS; j++) {
        float2 w2 = w_s[j][l];
        float2 ea = ea_s[j][w];
        float r = w2.x * s0 + w2.y * s1;          // read BEFORE update
        s0 = fmaf(w2.x, fmaf(-ea.x, s0, ea.y), s0);
        s1 = fmaf(w2.y, fmaf(-ea.x, s1, ea.y), s1);
        mybuf[j][l] = r;
    }
    __syncwarp();

    float* rd = g_read + (b * TT + ch * CS) * 64 + d;
    if (l < 16) {
        const float4* rowp = (const float4*)&mybuf[l][0];
        float sum = 0.f;
#pragma unroll
        for (int k = 0; k < 8; k++) {
            float4 v = rowp[k];
            sum += (v.x + v.y) + (v.z + v.w);
        }
        rd[l * 64] = sum;
    }
    if (l < CS - 16) {
        const float4* rowp = (const float4*)&mybuf[16 + l][0];
        float sum = 0.f;
#pragma unroll
        for (int k = 0; k < 8; k++) {
            float4 v = rowp[k];
            sum += (v.x + v.y) + (v.z + v.w);
        }
        rd[(16 + l) * 64] = sum;
    }
}

// =====================================================================
// Kernel O: p = sigmoid( tanh(read·fW1^T + G[skill]) · pW^T + pb )
// =====================================================================
__global__ __launch_bounds__(256) void k_out(
    const float* __restrict__ fW, const float* __restrict__ pW,
    const float* __restrict__ pb, float* __restrict__ out)
{
    __shared__ __align__(16) float F1[64 * 68];

    int tid = threadIdx.x;
    {
        const float4* src = (const float4*)fW;
#pragma unroll
        for (int k = 0; k < 4; k++) {
            int i = tid + k * 256;
            int o = i >> 4, q4 = i & 15;
            *(float4*)&F1[o * 68 + q4 * 4] = src[o * 32 + q4];
        }
    }
    __syncthreads();

    int w = tid >> 5, l = tid & 31;
    const float4* pL = (const float4*)&F1[l * 68];
    const float4* pH = (const float4*)&F1[(l + 32) * 68];
    float pl = pW[l], ph = pW[l + 32];
    float pbv = pb[0];

    for (int rp = 0; rp < 2; rp++) {
        int row0 = blockIdx.x * 32 + w * 4 + rp * 2;
        int row1 = row0 + 1;
        int b0 = row0 / 199, t0 = row0 - b0 * 199 + 1;
        int b1 = row1 / 199, t1 = row1 - b1 * 199 + 1;
        int i0 = b0 * TT + t0, i1 = b1 * TT + t1;

        const float4* X0 = (const float4*)&g_read[i0 * 64];
        const float4* X1 = (const float4*)&g_read[i1 * 64];

        float a00 = 0.f, a01 = 0.f, a10 = 0.f, a11 = 0.f;
#pragma unroll
        for (int q = 0; q < 16; q++) {
            float4 xa = X0[q];
            float4 xb = X1[q];
            float4 mL = pL[q];
            float4 mH = pH[q];
            a00 = fmaf(xa.x, mL.x, a00); a00 = fmaf(xa.y, mL.y, a00);
            a00 = fmaf(xa.z, mL.z, a00); a00 = fmaf(xa.w, mL.w, a00);
            a01 = fmaf(xa.x, mH.x, a01); a01 = fmaf(xa.y, mH.y, a01);
            a01 = fmaf(xa.z, mH.z, a01); a01 = fmaf(xa.w, mH.w, a01);
            a10 = fmaf(xb.x, mL.x, a10); a10 = fmaf(xb.y, mL.y, a10);
            a10 = fmaf(xb.z, mL.z, a10); a10 = fmaf(xb.w, mL.w, a10);
            a11 = fmaf(xb.x, mH.x, a11); a11 = fmaf(xb.y, mH.y, a11);
            a11 = fmaf(xb.z, mH.z, a11); a11 = fmaf(xb.w, mH.w, a11);
        }

        int sk0 = g_idx[i0] & 0xffff;
        int sk1 = g_idx[i1] & 0xffff;
        float2 G0 = g_G[sk0 * 32 + l];
        float2 G1 = g_G[sk1 * 32 + l];

        float f00 = tanh_a(a00 + G0.x), f01 = tanh_a(a01 + G0.y);
        float f10 = tanh_a(a10 + G1.x), f11 = tanh_a(a11 + G1.y);

        float r0 = f00 * pl + f01 * ph;
        float r1 = f10 * pl + f11 * ph;
#pragma unroll
        for (int o = 16; o; o >>= 1) {
            r0 += __shfl_xor_sync(~0u, r0, o);
            r1 += __shfl_xor_sync(~0u, r1, o);
        }
        if (l == 0) {
            out[row0] = sigmoid_e(r0 + pbv);
            out[row1] = sigmoid_e(r1 + pbv);
        }
    }
}

// =====================================================================
// launch
// =====================================================================
extern "C" void kernel_launch(void* const* d_in, const int* in_sizes, int n_in,
                              void* d_out, int out_size) {
    const int*   skills    = (const int*)d_in[0];
    const int*   responses = (const int*)d_in[1];
    const float* k_emb     = (const float*)d_in[2];
    const float* v_emb     = (const float*)d_in[3];
    const float* Mk        = (const float*)d_in[4];
    const float* Mv0       = (const float*)d_in[5];
    const float* fW        = (const float*)d_in[6];
    const float* fb        = (const float*)d_in[7];
    const float* eW        = (const float*)d_in[8];
    const float* eb        = (const float*)d_in[9];
    const float* aW        = (const float*)d_in[10];
    const float* ab        = (const float*)d_in[11];
    const float* pW        = (const float*)d_in[12];
    const float* pb        = (const float*)d_in[13];
    float* out = (float*)d_out;

    k_pre <<<375, 256>>>(skills, responses, k_emb, v_emb, Mk, fW, fb, eW, eb, aW, ab);
    kA    <<<4096, 256>>>();
    kC    <<<4096, 256>>>(Mv0);
    k_out <<<398, 256>>>(fW, pW, pb, out);
}

// round 8
// speedup vs baseline: 1.6261x; 1.6261x over previous
#include <cuda_runtime.h>

#define BB 64
#define TT 200
#define NS 1000

// ---------------- device scratch ----------------
__device__ float2 g_Wsk[1000 * 32];   // (w[l], w[l+32]) per skill, softmaxed
__device__ float2 g_EA [2000 * 64];   // (e, a) per x-index, per d
__device__ float2 g_G  [1000 * 32];   // (g[l], g[l+32]) = k·fW2^T + fb
__device__ int    g_idx[BB * TT];     // skill | (x << 16)
__device__ float  g_read[BB * TT * 64];

static __device__ __forceinline__ float tanh_a(float x) {
    float y; asm("tanh.approx.f32 %0, %1;" : "=f"(y) : "f"(x)); return y;
}
static __device__ __forceinline__ float sigmoid_e(float x) {
    return 1.0f / (1.0f + __expf(-x));
}

// =====================================================================
// Kernel P: precompute tables. 1 row per warp. (round-6 version, 9.7us)
// =====================================================================
__global__ __launch_bounds__(256) void k_pre(
    const int* __restrict__ skills, const int* __restrict__ responses,
    const float* __restrict__ k_emb, const float* __restrict__ v_emb,
    const float* __restrict__ Mk, const float* __restrict__ fW,
    const float* __restrict__ fb, const float* __restrict__ eW,
    const float* __restrict__ eb, const float* __restrict__ aW,
    const float* __restrict__ ab)
{
    __shared__ __align__(16) float W0[64 * 68];
    __shared__ __align__(16) float W1[64 * 68];

    int tid = threadIdx.x;
    int w = tid >> 5, l = tid & 31;
    bool isA = blockIdx.x < 125;
    int row = isA ? (blockIdx.x * 8 + w) : ((blockIdx.x - 125) * 8 + w);

    const float4* xp = isA ? (const float4*)&k_emb[row * 64]
                           : (const float4*)&v_emb[row * 64];
    float4 xr[16];
#pragma unroll
    for (int q = 0; q < 16; q++) xr[q] = xp[q];

    int gt = blockIdx.x * 256 + tid;
    if (gt < BB * TT) {
        int s = skills[gt], r = responses[gt];
        int mr = (r > -1) ? r : 0;
        g_idx[gt] = s | ((s + NS * mr) << 16);
    }

    {
        const float4* s0 = isA ? (const float4*)Mk : (const float4*)eW;
        const float4* s1f = (const float4*)fW;
        const float4* s1a = (const float4*)aW;
        float4 v0[4], v1[4];
#pragma unroll
        for (int k = 0; k < 4; k++) {
            int i = tid + k * 256;
            int o = i >> 4, q4 = i & 15;
            v0[k] = s0[i];
            v1[k] = isA ? s1f[o * 32 + 16 + q4] : s1a[i];
        }
#pragma unroll
        for (int k = 0; k < 4; k++) {
            int i = tid + k * 256;
            int o = i >> 4, q4 = i & 15;
            *(float4*)&W0[o * 68 + q4 * 4] = v0[k];
            *(float4*)&W1[o * 68 + q4 * 4] = v1[k];
        }
    }
    __syncthreads();

    const float4* pL0 = (const float4*)&W0[l * 68];
    const float4* pH0 = (const float4*)&W0[(l + 32) * 68];
    const float4* pL1 = (const float4*)&W1[l * 68];
    const float4* pH1 = (const float4*)&W1[(l + 32) * 68];

    float c0A = 0.f, c1A = 0.f, c2A = 0.f, c3A = 0.f;
    float c0B = 0.f, c1B = 0.f, c2B = 0.f, c3B = 0.f;
#pragma unroll
    for (int q = 0; q < 16; q += 2) {
        float4 xa = xr[q];
        float4 xb = xr[q + 1];
        float4 aL = pL0[q];  float4 aL2 = pL0[q + 1];
        float4 aH = pH0[q];  float4 aH2 = pH0[q + 1];
        float4 bL = pL1[q];  float4 bL2 = pL1[q + 1];
        float4 bH = pH1[q];  float4 bH2 = pH1[q + 1];
        c0A = fmaf(xa.x, aL.x, c0A); c0A = fmaf(xa.y, aL.y, c0A);
        c0A = fmaf(xa.z, aL.z, c0A); c0A = fmaf(xa.w, aL.w, c0A);
        c1A = fmaf(xa.x, aH.x, c1A); c1A = fmaf(xa.y, aH.y, c1A);
        c1A = fmaf(xa.z, aH.z, c1A); c1A = fmaf(xa.w, aH.w, c1A);
        c2A = fmaf(xa.x, bL.x, c2A); c2A = fmaf(xa.y, bL.y, c2A);
        c2A = fmaf(xa.z, bL.z, c2A); c2A = fmaf(xa.w, bL.w, c2A);
        c3A = fmaf(xa.x, bH.x, c3A); c3A = fmaf(xa.y, bH.y, c3A);
        c3A = fmaf(xa.z, bH.z, c3A); c3A = fmaf(xa.w, bH.w, c3A);
        c0B = fmaf(xb.x, aL2.x, c0B); c0B = fmaf(xb.y, aL2.y, c0B);
        c0B = fmaf(xb.z, aL2.z, c0B); c0B = fmaf(xb.w, aL2.w, c0B);
        c1B = fmaf(xb.x, aH2.x, c1B); c1B = fmaf(xb.y, aH2.y, c1B);
        c1B = fmaf(xb.z, aH2.z, c1B); c1B = fmaf(xb.w, aH2.w, c1B);
        c2B = fmaf(xb.x, bL2.x, c2B); c2B = fmaf(xb.y, bL2.y, c2B);
        c2B = fmaf(xb.z, bL2.z, c2B); c2B = fmaf(xb.w, bL2.w, c2B);
        c3B = fmaf(xb.x, bH2.x, c3B); c3B = fmaf(xb.y, bH2.y, c3B);
        c3B = fmaf(xb.z, bH2.z, c3B); c3B = fmaf(xb.w, bH2.w, c3B);
    }
    float c0 = c0A + c0B, c1 = c1A + c1B;
    float c2 = c2A + c2B, c3 = c3A + c3B;

    if (isA) {
        float e0 = __expf(c0), e1 = __expf(c1);
        float s = e0 + e1;
#pragma unroll
        for (int o = 16; o; o >>= 1) s += __shfl_xor_sync(~0u, s, o);
        float inv = 1.0f / s;
        g_Wsk[row * 32 + l] = make_float2(e0 * inv, e1 * inv);
        g_G[row * 32 + l]   = make_float2(c2 + fb[l], c3 + fb[l + 32]);
    } else {
        g_EA[row * 64 + l]      = make_float2(sigmoid_e(c0 + eb[l]),      tanhf(c2 + ab[l]));
        g_EA[row * 64 + l + 32] = make_float2(sigmoid_e(c1 + eb[l + 32]), tanhf(c3 + ab[l + 32]));
    }
}

// =====================================================================
// Kernel S: scan (round-6 version, ~20us). 4096 warps; block = 8 warps,
// same b, d = 8*(blockIdx&7)+w. Register-pipelined double-buffered
// staging; LDS-only inner loop; deferred transposed read-reduction.
// =====================================================================
__global__ __launch_bounds__(256) void k_scan(const float* __restrict__ Mv0)
{
    __shared__ __align__(16) float2 w_s[2][32][32];   // 16KB
    __shared__ __align__(16) float2 ea_s[2][32][8];   //  4KB
    __shared__ __align__(16) float  buf[8][16][36];   // 18KB

    int tid = threadIdx.x;
    int w = tid >> 5, l = tid & 31;
    int b = blockIdx.x >> 3;
    int dbase = (blockIdx.x & 7) << 3;
    int d = dbase + w;

    float s0 = Mv0[l * 64 + d];
    float s1 = Mv0[(l + 32) * 64 + d];

    const int* idxp = g_idx + b * TT;
    float* rd = g_read + b * TT * 64 + d;
    float (*mybuf)[36] = buf[w];

    int est = tid >> 3, edl = tid & 7;

    float2 wv[4], eav;
#pragma unroll
    for (int k = 0; k < 4; k++) {
        int p = idxp[w + 8 * k];
        wv[k] = g_Wsk[(p & 0xffff) * 32 + l];
    }
    {
        int pe = idxp[est];
        eav = g_EA[(pe >> 16) * 64 + dbase + edl];
    }
#pragma unroll
    for (int k = 0; k < 4; k++) w_s[0][w + 8 * k][l] = wv[k];
    ea_s[0][est][edl] = eav;
    __syncthreads();

    for (int c = 0; c < 6; c++) {
        int cur = c & 1;
        if (c < 5) {
            int t0n = (c + 1) * 32;
#pragma unroll
            for (int k = 0; k < 4; k++) {
                int p = idxp[t0n + w + 8 * k];
                wv[k] = g_Wsk[(p & 0xffff) * 32 + l];
            }
            int pe = idxp[t0n + est];
            eav = g_EA[(pe >> 16) * 64 + dbase + edl];
        } else {
#pragma unroll
            for (int k = 0; k < 4; k++) {
                int st = w + 8 * k; st = st < 8 ? st : 7;
                int p = idxp[192 + st];
                wv[k] = g_Wsk[(p & 0xffff) * 32 + l];
            }
            int st2 = est < 8 ? est : 7;
            int pe = idxp[192 + st2];
            eav = g_EA[(pe >> 16) * 64 + dbase + edl];
        }

        int t0 = c * 32;
#pragma unroll
        for (int h = 0; h < 2; h++) {
#pragma unroll
            for (int j = 0; j < 16; j++) {
                int t = h * 16 + j;
                float2 w2 = w_s[cur][t][l];
                float2 ea = ea_s[cur][t][w];
                float r = w2.x * s0 + w2.y * s1;          // read BEFORE update
                s0 = fmaf(w2.x, fmaf(-ea.x, s0, ea.y), s0);
                s1 = fmaf(w2.y, fmaf(-ea.x, s1, ea.y), s1);
                mybuf[j][l] = r;
            }
            __syncwarp();
            if (l < 16) {
                const float4* rowp = (const float4*)&mybuf[l][0];
                float sum = 0.f;
#pragma unroll
                for (int k = 0; k < 8; k++) {
                    float4 v = rowp[k];
                    sum += (v.x + v.y) + (v.z + v.w);
                }
                rd[(t0 + h * 16 + l) * 64] = sum;
            }
            __syncwarp();
        }

        int nb = cur ^ 1;
#pragma unroll
        for (int k = 0; k < 4; k++) w_s[nb][w + 8 * k][l] = wv[k];
        ea_s[nb][est][edl] = eav;
        __syncthreads();
    }

    {
#pragma unroll
        for (int j = 0; j < 8; j++) {
            float2 w2 = w_s[0][j][l];
            float2 ea = ea_s[0][j][w];
            float r = w2.x * s0 + w2.y * s1;
            s0 = fmaf(w2.x, fmaf(-ea.x, s0, ea.y), s0);
            s1 = fmaf(w2.y, fmaf(-ea.x, s1, ea.y), s1);
            mybuf[j][l] = r;
        }
        __syncwarp();
        if (l < 8) {
            const float4* rowp = (const float4*)&mybuf[l][0];
            float sum = 0.f;
#pragma unroll
            for (int k = 0; k < 8; k++) {
                float4 v = rowp[k];
                sum += (v.x + v.y) + (v.z + v.w);
            }
            rd[(192 + l) * 64] = sum;
        }
    }
}

// =====================================================================
// Kernel O: p = sigmoid( tanh(read·fW1^T + G[skill]) · pW^T + pb )
// smem staging for read vectors (keeps register count low), 2 rows/warp,
// 2 iterations; launch_bounds caps regs to preserve occupancy.
// =====================================================================
__global__ __launch_bounds__(256, 5) void k_out(
    const float* __restrict__ fW, const float* __restrict__ pW,
    const float* __restrict__ pb, float* __restrict__ out)
{
    __shared__ __align__(16) float F1[64 * 68];
    __shared__ __align__(16) float x_s[8][2][64];

    int tid = threadIdx.x;
    {
        const float4* src = (const float4*)fW;
#pragma unroll
        for (int k = 0; k < 4; k++) {
            int i = tid + k * 256;
            int o = i >> 4, q4 = i & 15;
            *(float4*)&F1[o * 68 + q4 * 4] = src[o * 32 + q4];
        }
    }
    __syncthreads();

    int w = tid >> 5, l = tid & 31;
    const float4* pL = (const float4*)&F1[l * 68];
    const float4* pH = (const float4*)&F1[(l + 32) * 68];
    float pl = pW[l], ph = pW[l + 32];
    float pbv = pb[0];

    for (int rp = 0; rp < 2; rp++) {
        int row0 = blockIdx.x * 32 + w * 4 + rp * 2;
        int row1 = row0 + 1;
        int b0 = row0 / 199, t0 = row0 - b0 * 199 + 1;
        int b1 = row1 / 199, t1 = row1 - b1 * 199 + 1;
        int i0 = b0 * TT + t0, i1 = b1 * TT + t1;

        *(float2*)&x_s[w][0][2 * l] = ((const float2*)&g_read[i0 * 64])[l];
        *(float2*)&x_s[w][1][2 * l] = ((const float2*)&g_read[i1 * 64])[l];
        __syncwarp();

        float a00 = 0.f, a01 = 0.f, a10 = 0.f, a11 = 0.f;
#pragma unroll
        for (int q = 0; q < 16; q++) {
            float4 xa = *(const float4*)&x_s[w][0][q * 4];
            float4 xb = *(const float4*)&x_s[w][1][q * 4];
            float4 mL = pL[q];
            float4 mH = pH[q];
            a00 = fmaf(xa.x, mL.x, a00); a00 = fmaf(xa.y, mL.y, a00);
            a00 = fmaf(xa.z, mL.z, a00); a00 = fmaf(xa.w, mL.w, a00);
            a01 = fmaf(xa.x, mH.x, a01); a01 = fmaf(xa.y, mH.y, a01);
            a01 = fmaf(xa.z, mH.z, a01); a01 = fmaf(xa.w, mH.w, a01);
            a10 = fmaf(xb.x, mL.x, a10); a10 = fmaf(xb.y, mL.y, a10);
            a10 = fmaf(xb.z, mL.z, a10); a10 = fmaf(xb.w, mL.w, a10);
            a11 = fmaf(xb.x, mH.x, a11); a11 = fmaf(xb.y, mH.y, a11);
            a11 = fmaf(xb.z, mH.z, a11); a11 = fmaf(xb.w, mH.w, a11);
        }

        int sk0 = g_idx[i0] & 0xffff;
        int sk1 = g_idx[i1] & 0xffff;
        float2 G0 = g_G[sk0 * 32 + l];
        float2 G1 = g_G[sk1 * 32 + l];

        float f00 = tanh_a(a00 + G0.x), f01 = tanh_a(a01 + G0.y);
        float f10 = tanh_a(a10 + G1.x), f11 = tanh_a(a11 + G1.y);

        float r0 = f00 * pl + f01 * ph;
        float r1 = f10 * pl + f11 * ph;
#pragma unroll
        for (int o = 16; o; o >>= 1) {
            r0 += __shfl_xor_sync(~0u, r0, o);
            r1 += __shfl_xor_sync(~0u, r1, o);
        }
        if (l == 0) {
            out[row0] = sigmoid_e(r0 + pbv);
            out[row1] = sigmoid_e(r1 + pbv);
        }
        __syncwarp();
    }
}

// =====================================================================
// launch
// =====================================================================
extern "C" void kernel_launch(void* const* d_in, const int* in_sizes, int n_in,
                              void* d_out, int out_size) {
    const int*   skills    = (const int*)d_in[0];
    const int*   responses = (const int*)d_in[1];
    const float* k_emb     = (const float*)d_in[2];
    const float* v_emb     = (const float*)d_in[3];
    const float* Mk        = (const float*)d_in[4];
    const float* Mv0       = (const float*)d_in[5];
    const float* fW        = (const float*)d_in[6];
    const float* fb        = (const float*)d_in[7];
    const float* eW        = (const float*)d_in[8];
    const float* eb        = (const float*)d_in[9];
    const float* aW        = (const float*)d_in[10];
    const float* ab        = (const float*)d_in[11];
    const float* pW        = (const float*)d_in[12];
    const float* pb        = (const float*)d_in[13];
    float* out = (float*)d_out;

    k_pre <<<375, 256>>>(skills, responses, k_emb, v_emb, Mk, fW, fb, eW, eb, aW, ab);
    k_scan<<<512, 256>>>(Mv0);
    k_out <<<398, 256>>>(fW, pW, pb, out);
}